// round 2
// baseline (speedup 1.0000x reference)
#include <cuda_runtime.h>

#define TT 512
#define BB 64
#define II 512
#define HH 512

// Static device scratch (no allocations allowed)
__device__ float g_xp[2][TT][BB][HH];   // input projections per direction (134 MB)
__device__ float g_h[2][2][BB][HH];     // [dir][buf][b][h] double-buffered state

// ---------------------------------------------------------------------------
// init hidden state from h0
// ---------------------------------------------------------------------------
__global__ void init_h_kernel(const float* __restrict__ h0f,
                              const float* __restrict__ h0b) {
    int i = blockIdx.x * blockDim.x + threadIdx.x;
    if (i < BB * HH) {
        ((float*)g_h[0][0])[i] = h0f[i];
        ((float*)g_h[1][0])[i] = h0b[i];
    }
}

// ---------------------------------------------------------------------------
// Phase 1: xp[dir][t][b][n] = sum_i x[b][t][i] * W[n][i] + bias[n]
// Grid (HH/64, TT, 2); 256 threads; 64x64 CTA tile; 4x4 per-thread tile.
// ---------------------------------------------------------------------------
__global__ __launch_bounds__(256) void xproj_kernel(
    const float* __restrict__ x,
    const float* __restrict__ Wf, const float* __restrict__ bf,
    const float* __restrict__ Wb, const float* __restrict__ bbias) {
    const int dir = blockIdx.z;
    const float* __restrict__ W    = dir ? Wb : Wf;
    const float* __restrict__ bias = dir ? bbias : bf;
    const int t  = blockIdx.y;
    const int n0 = blockIdx.x * 64;

    __shared__ float a_s[16][68];   // [k][m]   (m = batch)
    __shared__ float b_s[16][68];   // [k][n]

    const int tid = threadIdx.x;
    const int tx = tid & 15;        // n-frag (x4)
    const int ty = tid >> 4;        // m-frag (x4)
    const int lm = tid >> 2;        // loader row 0..63
    const int lk = (tid & 3) << 2;  // loader k offset 0,4,8,12

    const float* arow = x + ((size_t)lm * TT + t) * II;    // batch lm at time t
    const float* brow = W + (size_t)(n0 + lm) * II;

    float acc[4][4] = {};
    for (int kt = 0; kt < II / 16; kt++) {
        float4 pa = *(const float4*)(arow + kt * 16 + lk);
        float4 pb = *(const float4*)(brow + kt * 16 + lk);
        a_s[lk + 0][lm] = pa.x; a_s[lk + 1][lm] = pa.y;
        a_s[lk + 2][lm] = pa.z; a_s[lk + 3][lm] = pa.w;
        b_s[lk + 0][lm] = pb.x; b_s[lk + 1][lm] = pb.y;
        b_s[lk + 2][lm] = pb.z; b_s[lk + 3][lm] = pb.w;
        __syncthreads();
#pragma unroll
        for (int k = 0; k < 16; k++) {
            float4 av = *(const float4*)&a_s[k][ty << 2];
            float4 bv = *(const float4*)&b_s[k][tx << 2];
            float am[4] = {av.x, av.y, av.z, av.w};
            float bn[4] = {bv.x, bv.y, bv.z, bv.w};
#pragma unroll
            for (int i = 0; i < 4; i++)
#pragma unroll
                for (int j = 0; j < 4; j++)
                    acc[i][j] += am[i] * bn[j];
        }
        __syncthreads();
    }

    float4 bv = *(const float4*)(bias + n0 + (tx << 2));
#pragma unroll
    for (int i = 0; i < 4; i++) {
        int b = (ty << 2) + i;
        float4 v;
        v.x = acc[i][0] + bv.x; v.y = acc[i][1] + bv.y;
        v.z = acc[i][2] + bv.z; v.w = acc[i][3] + bv.w;
        *(float4*)&g_xp[dir][t][b][n0 + (tx << 2)] = v;
    }
}

// ---------------------------------------------------------------------------
// Phase 2: one recurrence step, both directions.
// h_new[b][n] = tanh(xp[dir][t][b][n] + sum_k h[b][k] * Wh[n][k])
// Grid (64, 2); 256 threads; CTA = 64 batches x 8 cols; 2 outputs/thread.
// ---------------------------------------------------------------------------
__global__ __launch_bounds__(256) void rnn_step_kernel(
    int s, const float* __restrict__ Whf, const float* __restrict__ Whb,
    float* __restrict__ out) {
    const int dir = blockIdx.y;
    const float* __restrict__ Wh = dir ? Whb : Whf;
    const int t = dir ? (TT - 1 - s) : s;
    const int n0 = blockIdx.x * 8;
    const int buf = s & 1;
    const float* __restrict__ hin = (const float*)g_h[dir][buf];
    float* __restrict__ hout = (float*)g_h[dir][buf ^ 1];

    __shared__ float h_s[64][132];   // [b][k] chunk, padded
    __shared__ float w_s[8][132];    // [n_local][k] chunk

    const int tid = threadIdx.x;
    const int tx = tid & 7;          // local output col
    const int ty = tid >> 3;         // 0..31 -> batches 2ty, 2ty+1
    const int b0 = ty << 1;

    float acc0 = 0.f, acc1 = 0.f;

    for (int kt = 0; kt < 4; kt++) {
        const int k0 = kt * 128;
        // stage h chunk: 64 x 128 floats = 2048 float4, 8 per thread
#pragma unroll
        for (int i = 0; i < 8; i++) {
            int e = i * 256 + tid;
            int b = e >> 5, k4 = e & 31;
            *(float4*)&h_s[b][k4 << 2] =
                *(const float4*)(hin + b * HH + k0 + (k4 << 2));
        }
        // stage w chunk: 8 x 128 floats = 256 float4, 1 per thread
        {
            int wn = tid >> 5, k4 = tid & 31;
            *(float4*)&w_s[wn][k4 << 2] =
                *(const float4*)(Wh + (size_t)(n0 + wn) * HH + k0 + (k4 << 2));
        }
        __syncthreads();
#pragma unroll 8
        for (int k4 = 0; k4 < 32; k4++) {
            float4 w = *(const float4*)&w_s[tx][k4 << 2];
            float4 a = *(const float4*)&h_s[b0][k4 << 2];
            float4 c = *(const float4*)&h_s[b0 + 1][k4 << 2];
            acc0 += a.x * w.x + a.y * w.y + a.z * w.z + a.w * w.w;
            acc1 += c.x * w.x + c.y * w.y + c.z * w.z + c.w * w.w;
        }
        __syncthreads();
    }

    const int n = n0 + tx;
    const float* __restrict__ xp = &g_xp[dir][t][0][0];
    float v0 = tanhf(acc0 + xp[(size_t)b0 * HH + n]);
    float v1 = tanhf(acc1 + xp[(size_t)(b0 + 1) * HH + n]);
    hout[b0 * HH + n] = v0;
    hout[(b0 + 1) * HH + n] = v1;

    // y: (B, T, 2H)
    out[((size_t)b0 * TT + t) * (2 * HH) + (size_t)dir * HH + n] = v0;
    out[((size_t)(b0 + 1) * TT + t) * (2 * HH) + (size_t)dir * HH + n] = v1;

    if (s == TT - 1) {
        float* hT = out + (size_t)BB * TT * 2 * HH + (size_t)dir * BB * HH;
        hT[b0 * HH + n] = v0;
        hT[(b0 + 1) * HH + n] = v1;
    }
}

extern "C" void kernel_launch(void* const* d_in, const int* in_sizes, int n_in,
                              void* d_out, int out_size) {
    const float* x     = (const float*)d_in[0];
    const float* h0f   = (const float*)d_in[1];
    const float* h0b   = (const float*)d_in[2];
    const float* Wxf_w = (const float*)d_in[3];
    const float* Wxf_b = (const float*)d_in[4];
    const float* Whf_w = (const float*)d_in[5];
    const float* Wxb_w = (const float*)d_in[6];
    const float* Wxb_b = (const float*)d_in[7];
    const float* Whb_w = (const float*)d_in[8];
    float* out = (float*)d_out;

    init_h_kernel<<<(BB * HH + 255) / 256, 256>>>(h0f, h0b);
    xproj_kernel<<<dim3(HH / 64, TT, 2), 256>>>(x, Wxf_w, Wxf_b, Wxb_w, Wxb_b);
    for (int s = 0; s < TT; s++)
        rnn_step_kernel<<<dim3(64, 2), 256>>>(s, Whf_w, Whb_w, out);
}

// round 3
// speedup vs baseline: 1.0918x; 1.0918x over previous
#include <cuda_runtime.h>

#define TT 512
#define BB 64
#define II 512
#define HH 512

// Static device scratch (no allocations allowed)
__device__ float g_xp[2][TT][BB][HH];   // input projections per direction (134 MB)
__device__ float g_h[2][2][BB][HH];     // [dir][buf][b][h] double-buffered state
__device__ unsigned g_bar[2];           // per-direction grid barrier counters

typedef unsigned long long ull;

__device__ __forceinline__ void fma2(ull& acc, ull a, ull b) {
    asm("fma.rn.f32x2 %0, %1, %2, %0;" : "+l"(acc) : "l"(a), "l"(b));
}
__device__ __forceinline__ ull add2(ull a, ull b) {
    ull r; asm("add.rn.f32x2 %0, %1, %2;" : "=l"(r) : "l"(a), "l"(b)); return r;
}
__device__ __forceinline__ float2 unpack2(ull v) {
    float2 r; asm("mov.b64 {%0, %1}, %2;" : "=f"(r.x), "=f"(r.y) : "l"(v)); return r;
}
__device__ __forceinline__ unsigned ld_acq(const unsigned* p) {
    unsigned v; asm volatile("ld.acquire.gpu.u32 %0, [%1];" : "=r"(v) : "l"(p) : "memory");
    return v;
}

// ---------------------------------------------------------------------------
// init: hidden state from h0, reset barrier counters
// ---------------------------------------------------------------------------
__global__ void init_h_kernel(const float* __restrict__ h0f,
                              const float* __restrict__ h0b) {
    int i = blockIdx.x * blockDim.x + threadIdx.x;
    if (i < BB * HH) {
        ((float*)g_h[0][0])[i] = h0f[i];
        ((float*)g_h[1][0])[i] = h0b[i];
    }
    if (i == 0) { g_bar[0] = 0u; g_bar[1] = 0u; }
}

// ---------------------------------------------------------------------------
// Phase 1: xp[dir][t][b][n] = sum_i x[b][t][i] * W[n][i] + bias[n]
// Grid (8, 512, 2); 256 threads; 64x64 tile; packed f32x2 FMA.
// ---------------------------------------------------------------------------
__global__ __launch_bounds__(256) void xproj_kernel(
    const float* __restrict__ x,
    const float* __restrict__ Wf, const float* __restrict__ bf,
    const float* __restrict__ Wb, const float* __restrict__ bbias) {
    const int dir = blockIdx.z;
    const float* __restrict__ W    = dir ? Wb : Wf;
    const float* __restrict__ bias = dir ? bbias : bf;
    const int t  = blockIdx.y;
    const int n0 = blockIdx.x * 64;

    __shared__ float2 a2_s[16][66];   // [k][m] duplicated pairs (m = batch)
    __shared__ float  b_s[16][68];    // [k][n]

    const int tid = threadIdx.x;
    const int tx = tid & 15;          // n-frag (x4)
    const int ty = tid >> 4;          // m-frag (x4)
    const int lm = tid >> 2;          // loader row 0..63
    const int lk = (tid & 3) << 2;    // loader k offset

    const float* arow = x + ((size_t)lm * TT + t) * II;
    const float* brow = W + (size_t)(n0 + lm) * II;

    ull accA[4] = {0ull,0ull,0ull,0ull};   // n pair (4tx, 4tx+1)
    ull accB[4] = {0ull,0ull,0ull,0ull};   // n pair (4tx+2, 4tx+3)

    for (int kt = 0; kt < II / 16; kt++) {
        float4 pa = *(const float4*)(arow + kt * 16 + lk);
        float4 pb = *(const float4*)(brow + kt * 16 + lk);
        a2_s[lk + 0][lm] = make_float2(pa.x, pa.x);
        a2_s[lk + 1][lm] = make_float2(pa.y, pa.y);
        a2_s[lk + 2][lm] = make_float2(pa.z, pa.z);
        a2_s[lk + 3][lm] = make_float2(pa.w, pa.w);
        b_s[lk + 0][lm] = pb.x; b_s[lk + 1][lm] = pb.y;
        b_s[lk + 2][lm] = pb.z; b_s[lk + 3][lm] = pb.w;
        __syncthreads();
#pragma unroll
        for (int k = 0; k < 16; k++) {
            ulonglong2 bp = *(const ulonglong2*)&b_s[k][tx << 2];
            ull a0 = *(const ull*)&a2_s[k][(ty << 2) + 0];
            ull a1 = *(const ull*)&a2_s[k][(ty << 2) + 1];
            ull a2v = *(const ull*)&a2_s[k][(ty << 2) + 2];
            ull a3 = *(const ull*)&a2_s[k][(ty << 2) + 3];
            fma2(accA[0], a0, bp.x); fma2(accB[0], a0, bp.y);
            fma2(accA[1], a1, bp.x); fma2(accB[1], a1, bp.y);
            fma2(accA[2], a2v, bp.x); fma2(accB[2], a2v, bp.y);
            fma2(accA[3], a3, bp.x); fma2(accB[3], a3, bp.y);
        }
        __syncthreads();
    }

    float4 bv = *(const float4*)(bias + n0 + (tx << 2));
#pragma unroll
    for (int i = 0; i < 4; i++) {
        int b = (ty << 2) + i;
        float2 vA = unpack2(accA[i]);
        float2 vB = unpack2(accB[i]);
        float4 v;
        v.x = vA.x + bv.x; v.y = vA.y + bv.y;
        v.z = vB.x + bv.z; v.w = vB.y + bv.w;
        *(float4*)&g_xp[dir][t][b][n0 + (tx << 2)] = v;
    }
}

// ---------------------------------------------------------------------------
// Phase 2: persistent recurrence. 128 CTAs (64 per dir), all co-resident.
// CTA tile: 16 batches x 32 cols. Wh slice resident in SMEM for all 512 steps.
// Per-direction grid barrier between steps.
// ---------------------------------------------------------------------------
__global__ __launch_bounds__(256, 1) void rnn_persist(
    const float* __restrict__ Whf, const float* __restrict__ Whb,
    float* __restrict__ out) {
    extern __shared__ char smem[];
    float4* w4 = (float4*)smem;                    // [256 k2][16 n2] interleaved
    float2* hdup = (float2*)(smem + 65536);        // [16 b][514] duplicated pairs

    const int cta = blockIdx.x;
    const int dir = cta >> 6;
    const int slice = cta & 63;
    const int b_base = (slice >> 4) * 16;          // 4 batch slices
    const int n_base = (slice & 15) * 32;          // 16 col slices
    const float* __restrict__ Wh = dir ? Whb : Whf;
    const int tid = threadIdx.x;
    const int n2 = tid & 15;                       // n-pair index
    const int brow = tid >> 4;                     // 0..15
    const int b = b_base + brow;
    const int n = n_base + n2 * 2;

    // One-time fill of the weight tile:
    // w4[k2][n2] = {W[2n2][2k2], W[2n2+1][2k2], W[2n2][2k2+1], W[2n2+1][2k2+1]}
    {
        float* w4f = (float*)w4;
        for (int i = 0; i < 16; i++) {
            int e = i * 256 + tid;
            int nl = e >> 7;                       // 0..31 local col
            int c4 = e & 127;
            int k = c4 * 4;
            float4 w = *(const float4*)(Wh + (size_t)(n_base + nl) * HH + k);
            int j = nl >> 1, odd = nl & 1;
            float vv[4] = {w.x, w.y, w.z, w.w};
#pragma unroll
            for (int kk = 0; kk < 4; kk++) {
                int kg = k + kk;
                w4f[(((kg >> 1) * 16) + j) * 4 + (kg & 1) * 2 + odd] = vv[kk];
            }
        }
    }

    const ulonglong2* wp = (const ulonglong2*)w4 + n2;
    const ulonglong2* hp = (const ulonglong2*)(hdup + brow * 514);
    unsigned* barp = &g_bar[dir];

    for (int s = 0; s < TT; s++) {
        const int t = dir ? (TT - 1 - s) : s;
        const float* __restrict__ hin  = (const float*)g_h[dir][s & 1];
        float* __restrict__ hout = (float*)g_h[dir][(s & 1) ^ 1];

        // stage h slice (16 x 512) as duplicated pairs
        __syncthreads();   // protect hdup from previous step's readers
#pragma unroll
        for (int i = 0; i < 8; i++) {
            int e = i * 256 + tid;
            int r = e >> 7;
            int c4 = e & 127;
            float4 v = *(const float4*)(hin + (size_t)(b_base + r) * HH + c4 * 4);
            float2* d = hdup + r * 514 + c4 * 4;
            d[0] = make_float2(v.x, v.x);
            d[1] = make_float2(v.y, v.y);
            d[2] = make_float2(v.z, v.z);
            d[3] = make_float2(v.w, v.w);
        }
        __syncthreads();

        ull ae[2] = {0ull, 0ull}, ao[2] = {0ull, 0ull};
#pragma unroll 8
        for (int k2 = 0; k2 < 256; k2++) {
            ulonglong2 wv = wp[k2 * 16];   // (even-k n-pair, odd-k n-pair)
            ulonglong2 hv = hp[k2];        // ({he,he}, {ho,ho})
            fma2(ae[k2 & 1], hv.x, wv.x);
            fma2(ao[k2 & 1], hv.y, wv.y);
        }
        float2 sum = unpack2(add2(add2(ae[0], ae[1]), add2(ao[0], ao[1])));

        float2 xpv = *(const float2*)&g_xp[dir][t][b][n];
        float v0 = tanhf(sum.x + xpv.x);
        float v1 = tanhf(sum.y + xpv.y);
        *(float2*)(hout + (size_t)b * HH + n) = make_float2(v0, v1);
        *(float2*)(out + ((size_t)b * TT + t) * (2 * HH) + (size_t)dir * HH + n) =
            make_float2(v0, v1);
        if (s == TT - 1) {
            float* hT = out + (size_t)BB * TT * 2 * HH + (size_t)dir * BB * HH;
            *(float2*)(hT + (size_t)b * HH + n) = make_float2(v0, v1);
            break;  // no barrier needed after final step
        }

        // per-direction grid barrier
        __threadfence();
        __syncthreads();
        if (tid == 0) {
            atomicAdd(barp, 1u);
            unsigned target = 64u * (unsigned)(s + 1);
            while (ld_acq(barp) < target) {}
            __threadfence();
        }
        __syncthreads();
    }
}

extern "C" void kernel_launch(void* const* d_in, const int* in_sizes, int n_in,
                              void* d_out, int out_size) {
    const float* x     = (const float*)d_in[0];
    const float* h0f   = (const float*)d_in[1];
    const float* h0b   = (const float*)d_in[2];
    const float* Wxf_w = (const float*)d_in[3];
    const float* Wxf_b = (const float*)d_in[4];
    const float* Whf_w = (const float*)d_in[5];
    const float* Wxb_w = (const float*)d_in[6];
    const float* Wxb_b = (const float*)d_in[7];
    const float* Whb_w = (const float*)d_in[8];
    float* out = (float*)d_out;

    static int smem_set = 0;
    const int smem_bytes = 65536 + 16 * 514 * 8;   // 131328
    if (!smem_set) {
        cudaFuncSetAttribute(rnn_persist,
                             cudaFuncAttributeMaxDynamicSharedMemorySize,
                             smem_bytes);
        smem_set = 1;
    }

    init_h_kernel<<<(BB * HH + 255) / 256, 256>>>(h0f, h0b);
    xproj_kernel<<<dim3(HH / 64, TT, 2), 256>>>(x, Wxf_w, Wxf_b, Wxb_w, Wxb_b);
    rnn_persist<<<128, 256, smem_bytes>>>(Whf_w, Whb_w, out);
}

// round 4
// speedup vs baseline: 1.4427x; 1.3214x over previous
#include <cuda_runtime.h>

#define TT 512
#define BB 64
#define II 512
#define HH 512

#define WS_STRIDE 34   // float2 per k2 row for weights (32 used, padded)
#define HS_STRIDE 18   // float2 per k2 row for h (16 used, padded)

// Static device scratch (no allocations allowed)
__device__ float g_xp[2][TT][BB][HH];   // input projections per direction
__device__ float g_h[2][2][BB][HH];     // [dir][buf][b][h] double-buffered state
__device__ unsigned g_bar[2];           // per-direction grid barrier counters

typedef unsigned long long ull;

__device__ __forceinline__ void fma2(ull& acc, ull a, ull b) {
    asm("fma.rn.f32x2 %0, %1, %2, %0;" : "+l"(acc) : "l"(a), "l"(b));
}
__device__ __forceinline__ float2 unpack2(ull v) {
    float2 r; asm("mov.b64 {%0, %1}, %2;" : "=f"(r.x), "=f"(r.y) : "l"(v)); return r;
}
__device__ __forceinline__ unsigned ld_acq(const unsigned* p) {
    unsigned v; asm volatile("ld.acquire.gpu.u32 %0, [%1];" : "=r"(v) : "l"(p) : "memory");
    return v;
}

// ---------------------------------------------------------------------------
__global__ void init_h_kernel(const float* __restrict__ h0f,
                              const float* __restrict__ h0b) {
    int i = blockIdx.x * blockDim.x + threadIdx.x;
    if (i < BB * HH) {
        ((float*)g_h[0][0])[i] = h0f[i];
        ((float*)g_h[1][0])[i] = h0b[i];
    }
    if (i == 0) { g_bar[0] = 0u; g_bar[1] = 0u; }
}

// ---------------------------------------------------------------------------
// Phase 1: xp[dir][t][b][n] = sum_i x[b][t][i] * W[n][i] + bias[n]
// Grid (8, 512, 2); 256 threads; 64x64 tile; 4x4 thread tile; k-parity packed.
// ---------------------------------------------------------------------------
__global__ __launch_bounds__(256) void xproj_kernel(
    const float* __restrict__ x,
    const float* __restrict__ Wf, const float* __restrict__ bf,
    const float* __restrict__ Wb, const float* __restrict__ bbias) {
    const int dir = blockIdx.z;
    const float* __restrict__ W    = dir ? Wb : Wf;
    const float* __restrict__ bias = dir ? bbias : bf;
    const int t = blockIdx.y;
    const int n_base = blockIdx.x * 64;

    __shared__ float2 a2[8][66];   // [k2][m]  {x[m][2k2], x[m][2k2+1]}
    __shared__ float2 b2[8][66];   // [k2][n]

    const int tid = threadIdx.x;
    const int w = tid >> 5, lane = tid & 31;
    const int mgrp = ((w >> 1) << 2) | (lane >> 3);  // 0..15
    const int ngrp = ((w & 1) << 3) | (lane & 7);    // 0..15
    const int m0 = mgrp << 2, n0l = ngrp << 2;

    const int lr = tid >> 2;          // loader row 0..63
    const int lq = (tid & 3) << 2;    // k offset 0,4,8,12
    const float* arow = x + ((size_t)lr * TT + t) * II + lq;
    const float* brow = W + (size_t)(n_base + lr) * II + lq;

    ull acc[4][4];
#pragma unroll
    for (int i = 0; i < 4; i++)
#pragma unroll
        for (int j = 0; j < 4; j++) acc[i][j] = 0ull;

    for (int st = 0; st < 32; st++) {
        float4 pa = *(const float4*)(arow + st * 16);
        float4 pb = *(const float4*)(brow + st * 16);
        __syncthreads();
        a2[(lq >> 1) + 0][lr] = make_float2(pa.x, pa.y);
        a2[(lq >> 1) + 1][lr] = make_float2(pa.z, pa.w);
        b2[(lq >> 1) + 0][lr] = make_float2(pb.x, pb.y);
        b2[(lq >> 1) + 1][lr] = make_float2(pb.z, pb.w);
        __syncthreads();
#pragma unroll
        for (int k2 = 0; k2 < 8; k2++) {
            ulonglong2 av0 = *(const ulonglong2*)&a2[k2][m0];
            ulonglong2 av1 = *(const ulonglong2*)&a2[k2][m0 + 2];
            ulonglong2 bv0 = *(const ulonglong2*)&b2[k2][n0l];
            ulonglong2 bv1 = *(const ulonglong2*)&b2[k2][n0l + 2];
            ull am[4] = {av0.x, av0.y, av1.x, av1.y};
            ull bn[4] = {bv0.x, bv0.y, bv1.x, bv1.y};
#pragma unroll
            for (int i = 0; i < 4; i++)
#pragma unroll
                for (int j = 0; j < 4; j++)
                    fma2(acc[i][j], am[i], bn[j]);
        }
    }

    float4 bv = *(const float4*)(bias + n_base + n0l);
#pragma unroll
    for (int i = 0; i < 4; i++) {
        float2 s0 = unpack2(acc[i][0]);
        float2 s1 = unpack2(acc[i][1]);
        float2 s2 = unpack2(acc[i][2]);
        float2 s3 = unpack2(acc[i][3]);
        float4 v;
        v.x = s0.x + s0.y + bv.x;
        v.y = s1.x + s1.y + bv.y;
        v.z = s2.x + s2.y + bv.z;
        v.w = s3.x + s3.y + bv.w;
        *(float4*)&g_xp[dir][t][m0 + i][n_base + n0l] = v;
    }
}

// ---------------------------------------------------------------------------
// Phase 2: persistent recurrence. 128 CTAs (64/dir), 128 threads each.
// CTA tile 16b x 32n; thread tile 2b x 2n; k-parity packed, no duplication.
// Wh slice SMEM-resident for all 512 steps; h staged transposed [k2][b].
// ---------------------------------------------------------------------------
__global__ __launch_bounds__(128, 1) void rnn_persist(
    const float* __restrict__ Whf, const float* __restrict__ Whb,
    float* __restrict__ out) {
    extern __shared__ char smem[];
    float2* ws = (float2*)smem;                            // [256][WS_STRIDE]
    float2* hs = (float2*)(smem + 256 * WS_STRIDE * 8);    // [256][HS_STRIDE]

    const int cta = blockIdx.x;
    const int dir = cta >> 6;
    const int slice = cta & 63;
    const int b_base = (slice >> 4) * 16;   // 4 b-slices
    const int n_base = (slice & 15) * 32;   // 16 n-slices
    const float* __restrict__ Wh = dir ? Whb : Whf;
    const int tid = threadIdx.x;
    const int w = tid >> 5, lane = tid & 31;
    const int bgrp = ((w >> 1) << 2) | (lane >> 3);   // 0..7
    const int ngrp = ((w & 1) << 3) | (lane & 7);     // 0..15
    const int b0 = b_base + 2 * bgrp;
    const int n0 = n_base + 2 * ngrp;

    // one-time weight fill: ws[k2][nl] = {W[n][2k2], W[n][2k2+1]}
    for (int idx = tid; idx < 32 * 256; idx += 128) {
        int nl = idx >> 8, k2 = idx & 255;
        ws[k2 * WS_STRIDE + nl] =
            *(const float2*)(Wh + (size_t)(n_base + nl) * HH + 2 * k2);
    }

    const int sb = tid >> 3;     // staging row 0..15
    const int sc = tid & 7;      // staging c base
    const float2* wsp = ws + 2 * ngrp;
    const float2* hsp = hs + 2 * bgrp;
    unsigned* barp = &g_bar[dir];

    for (int s = 0; s < TT; s++) {
        const int t = dir ? (TT - 1 - s) : s;
        const float* __restrict__ hin  = (const float*)g_h[dir][s & 1];
        float* __restrict__ hout = (float*)g_h[dir][(s & 1) ^ 1];

        __syncthreads();   // protect hs from previous step's readers
#pragma unroll
        for (int i = 0; i < 16; i++) {
            int c = sc + 8 * i;   // 0..127 (float4 chunks of k)
            float4 v = *(const float4*)(hin + (size_t)(b_base + sb) * HH + 4 * c);
            hs[(2 * c) * HS_STRIDE + sb]     = make_float2(v.x, v.y);
            hs[(2 * c + 1) * HS_STRIDE + sb] = make_float2(v.z, v.w);
        }
        // prefetch xp for this step while staging completes
        float2 xp0 = *(const float2*)&g_xp[dir][t][b0][n0];
        float2 xp1 = *(const float2*)&g_xp[dir][t][b0 + 1][n0];
        __syncthreads();

        ull a00 = 0ull, a01 = 0ull, a10 = 0ull, a11 = 0ull;
#pragma unroll 8
        for (int k2 = 0; k2 < 256; k2++) {
            ulonglong2 wv = *(const ulonglong2*)(wsp + k2 * WS_STRIDE);
            ulonglong2 hv = *(const ulonglong2*)(hsp + k2 * HS_STRIDE);
            fma2(a00, hv.x, wv.x); fma2(a01, hv.x, wv.y);
            fma2(a10, hv.y, wv.x); fma2(a11, hv.y, wv.y);
        }
        float2 s00 = unpack2(a00), s01 = unpack2(a01);
        float2 s10 = unpack2(a10), s11 = unpack2(a11);
        float v00 = tanhf(s00.x + s00.y + xp0.x);
        float v01 = tanhf(s01.x + s01.y + xp0.y);
        float v10 = tanhf(s10.x + s10.y + xp1.x);
        float v11 = tanhf(s11.x + s11.y + xp1.y);

        *(float2*)(hout + (size_t)b0 * HH + n0)       = make_float2(v00, v01);
        *(float2*)(hout + (size_t)(b0 + 1) * HH + n0) = make_float2(v10, v11);
        *(float2*)(out + ((size_t)b0 * TT + t) * (2 * HH) + (size_t)dir * HH + n0) =
            make_float2(v00, v01);
        *(float2*)(out + ((size_t)(b0 + 1) * TT + t) * (2 * HH) + (size_t)dir * HH + n0) =
            make_float2(v10, v11);

        if (s == TT - 1) {
            float* hT = out + (size_t)BB * TT * 2 * HH + (size_t)dir * BB * HH;
            *(float2*)(hT + (size_t)b0 * HH + n0)       = make_float2(v00, v01);
            *(float2*)(hT + (size_t)(b0 + 1) * HH + n0) = make_float2(v10, v11);
            break;
        }

        // per-direction grid barrier
        __threadfence();
        __syncthreads();
        if (tid == 0) {
            atomicAdd(barp, 1u);
            unsigned target = 64u * (unsigned)(s + 1);
            while (ld_acq(barp) < target) {}
            __threadfence();
        }
        __syncthreads();
    }
}

extern "C" void kernel_launch(void* const* d_in, const int* in_sizes, int n_in,
                              void* d_out, int out_size) {
    const float* x     = (const float*)d_in[0];
    const float* h0f   = (const float*)d_in[1];
    const float* h0b   = (const float*)d_in[2];
    const float* Wxf_w = (const float*)d_in[3];
    const float* Wxf_b = (const float*)d_in[4];
    const float* Whf_w = (const float*)d_in[5];
    const float* Wxb_w = (const float*)d_in[6];
    const float* Wxb_b = (const float*)d_in[7];
    const float* Whb_w = (const float*)d_in[8];
    float* out = (float*)d_out;

    static int smem_set = 0;
    const int smem_bytes = 256 * WS_STRIDE * 8 + 256 * HS_STRIDE * 8;  // 106496
    if (!smem_set) {
        cudaFuncSetAttribute(rnn_persist,
                             cudaFuncAttributeMaxDynamicSharedMemorySize,
                             smem_bytes);
        smem_set = 1;
    }

    init_h_kernel<<<(BB * HH + 255) / 256, 256>>>(h0f, h0b);
    xproj_kernel<<<dim3(HH / 64, TT, 2), 256>>>(x, Wxf_w, Wxf_b, Wxb_w, Wxb_b);
    rnn_persist<<<128, 128, smem_bytes>>>(Whf_w, Whb_w, out);
}

// round 5
// speedup vs baseline: 1.5422x; 1.0690x over previous
#include <cuda_runtime.h>

#define TT 512
#define BB 64
#define II 512
#define HH 512

#define WS_STRIDE 34   // float2 per k2 row for weights (32 used, padded)
#define HS_STRIDE 18   // float2 per k2 row for h (16 used, padded)

// Static device scratch (no allocations allowed)
__device__ float g_xp[2][TT][BB][HH];   // input projections per direction
__device__ float g_h[2][2][BB][HH];     // [dir][buf][b][h] double-buffered state
__device__ unsigned g_flag[2][64][32];  // per-CTA barrier flags, 128B padded

typedef unsigned long long ull;

__device__ __forceinline__ void fma2(ull& acc, ull a, ull b) {
    asm("fma.rn.f32x2 %0, %1, %2, %0;" : "+l"(acc) : "l"(a), "l"(b));
}
__device__ __forceinline__ ull add2(ull a, ull b) {
    ull r; asm("add.rn.f32x2 %0, %1, %2;" : "=l"(r) : "l"(a), "l"(b)); return r;
}
__device__ __forceinline__ float2 unpack2(ull v) {
    float2 r; asm("mov.b64 {%0, %1}, %2;" : "=f"(r.x), "=f"(r.y) : "l"(v)); return r;
}
__device__ __forceinline__ unsigned ld_acq(const unsigned* p) {
    unsigned v; asm volatile("ld.acquire.gpu.u32 %0, [%1];" : "=r"(v) : "l"(p) : "memory");
    return v;
}
__device__ __forceinline__ void st_rel(unsigned* p, unsigned v) {
    asm volatile("st.release.gpu.u32 [%0], %1;" :: "l"(p), "r"(v) : "memory");
}

// ---------------------------------------------------------------------------
__global__ void init_h_kernel(const float* __restrict__ h0f,
                              const float* __restrict__ h0b) {
    int i = blockIdx.x * blockDim.x + threadIdx.x;
    if (i < BB * HH) {
        ((float*)g_h[0][0])[i] = h0f[i];
        ((float*)g_h[1][0])[i] = h0b[i];
    }
    if (i < 128) {
        g_flag[i >> 6][i & 63][0] = 0u;
    }
}

// ---------------------------------------------------------------------------
// Phase 1: xp[dir][t][b][n] = sum_i x[b][t][i] * W[n][i] + bias[n]
// Grid (8, 512, 2); 256 threads; 64x64 tile; 4x4 thread tile; k-parity packed.
// ---------------------------------------------------------------------------
__global__ __launch_bounds__(256) void xproj_kernel(
    const float* __restrict__ x,
    const float* __restrict__ Wf, const float* __restrict__ bf,
    const float* __restrict__ Wb, const float* __restrict__ bbias) {
    const int dir = blockIdx.z;
    const float* __restrict__ W    = dir ? Wb : Wf;
    const float* __restrict__ bias = dir ? bbias : bf;
    const int t = blockIdx.y;
    const int n_base = blockIdx.x * 64;

    __shared__ float2 a2[8][66];   // [k2][m]  {x[m][2k2], x[m][2k2+1]}
    __shared__ float2 b2[8][66];   // [k2][n]

    const int tid = threadIdx.x;
    const int w = tid >> 5, lane = tid & 31;
    const int mgrp = ((w >> 1) << 2) | (lane >> 3);  // 0..15
    const int ngrp = ((w & 1) << 3) | (lane & 7);    // 0..15
    const int m0 = mgrp << 2, n0l = ngrp << 2;

    const int lr = tid >> 2;          // loader row 0..63
    const int lq = (tid & 3) << 2;    // k offset 0,4,8,12
    const float* arow = x + ((size_t)lr * TT + t) * II + lq;
    const float* brow = W + (size_t)(n_base + lr) * II + lq;

    ull acc[4][4];
#pragma unroll
    for (int i = 0; i < 4; i++)
#pragma unroll
        for (int j = 0; j < 4; j++) acc[i][j] = 0ull;

    for (int st = 0; st < 32; st++) {
        float4 pa = *(const float4*)(arow + st * 16);
        float4 pb = *(const float4*)(brow + st * 16);
        __syncthreads();
        a2[(lq >> 1) + 0][lr] = make_float2(pa.x, pa.y);
        a2[(lq >> 1) + 1][lr] = make_float2(pa.z, pa.w);
        b2[(lq >> 1) + 0][lr] = make_float2(pb.x, pb.y);
        b2[(lq >> 1) + 1][lr] = make_float2(pb.z, pb.w);
        __syncthreads();
#pragma unroll
        for (int k2 = 0; k2 < 8; k2++) {
            ulonglong2 av0 = *(const ulonglong2*)&a2[k2][m0];
            ulonglong2 av1 = *(const ulonglong2*)&a2[k2][m0 + 2];
            ulonglong2 bv0 = *(const ulonglong2*)&b2[k2][n0l];
            ulonglong2 bv1 = *(const ulonglong2*)&b2[k2][n0l + 2];
            ull am[4] = {av0.x, av0.y, av1.x, av1.y};
            ull bn[4] = {bv0.x, bv0.y, bv1.x, bv1.y};
#pragma unroll
            for (int i = 0; i < 4; i++)
#pragma unroll
                for (int j = 0; j < 4; j++)
                    fma2(acc[i][j], am[i], bn[j]);
        }
    }

    float4 bv = *(const float4*)(bias + n_base + n0l);
#pragma unroll
    for (int i = 0; i < 4; i++) {
        float2 s0 = unpack2(acc[i][0]);
        float2 s1 = unpack2(acc[i][1]);
        float2 s2 = unpack2(acc[i][2]);
        float2 s3 = unpack2(acc[i][3]);
        float4 v;
        v.x = s0.x + s0.y + bv.x;
        v.y = s1.x + s1.y + bv.y;
        v.z = s2.x + s2.y + bv.z;
        v.w = s3.x + s3.y + bv.w;
        *(float4*)&g_xp[dir][t][m0 + i][n_base + n0l] = v;
    }
}

// ---------------------------------------------------------------------------
// Phase 2: persistent recurrence. 128 CTAs (64/dir), 256 threads each.
// CTA tile 16b x 32n; thread tile 2b x 2n; k-split by 2 across warp halves.
// Wh slice SMEM-resident for all 512 steps; h staged transposed [k2][b].
// Distributed-flag grid barrier per direction.
// ---------------------------------------------------------------------------
__global__ __launch_bounds__(256, 1) void rnn_persist(
    const float* __restrict__ Whf, const float* __restrict__ Whb,
    float* __restrict__ out) {
    extern __shared__ char smem[];
    float2* ws = (float2*)smem;                            // [256][WS_STRIDE]
    float2* hs = (float2*)(smem + 256 * WS_STRIDE * 8);    // [256][HS_STRIDE]
    ulonglong2* red = (ulonglong2*)hs;                     // reuse for reduction

    const int cta = blockIdx.x;
    const int dir = cta >> 6;
    const int slice = cta & 63;
    const int b_base = (slice >> 4) * 16;   // 4 b-slices
    const int n_base = (slice & 15) * 32;   // 16 n-slices
    const float* __restrict__ Wh = dir ? Whb : Whf;
    const int tid = threadIdx.x;
    const int khalf = tid >> 7;             // 0: k2 0..127, 1: k2 128..255
    const int ctid = tid & 127;
    const int w = ctid >> 5, lane = ctid & 31;
    const int bgrp = ((w >> 1) << 2) | (lane >> 3);   // 0..7
    const int ngrp = ((w & 1) << 3) | (lane & 7);     // 0..15
    const int b0 = b_base + 2 * bgrp;
    const int n0 = n_base + 2 * ngrp;

    // one-time weight fill: ws[k2][nl] = {W[n][2k2], W[n][2k2+1]}
    for (int idx = tid; idx < 32 * 256; idx += 256) {
        int nl = idx >> 8, k2 = idx & 255;
        ws[k2 * WS_STRIDE + nl] =
            *(const float2*)(Wh + (size_t)(n_base + nl) * HH + 2 * k2);
    }

    const int sb = tid >> 4;     // staging row 0..15
    const int sc = tid & 15;     // staging col base
    const float2* wsp = ws + (size_t)khalf * 128 * WS_STRIDE + 2 * ngrp;
    const float2* hsp = hs + (size_t)khalf * 128 * HS_STRIDE + 2 * bgrp;
    unsigned* myflag = &g_flag[dir][slice][0];

    for (int s = 0; s < TT; s++) {
        const int t = dir ? (TT - 1 - s) : s;
        const float* __restrict__ hin  = (const float*)g_h[dir][s & 1];
        float* __restrict__ hout = (float*)g_h[dir][(s & 1) ^ 1];

        // stage h slice (16 x 512) transposed into hs: 4 float4 per thread
#pragma unroll
        for (int i = 0; i < 8; i++) {
            int c = sc + 16 * i;   // float4 chunk index 0..127
            float4 v = *(const float4*)(hin + (size_t)(b_base + sb) * HH + 4 * c);
            hs[(2 * c) * HS_STRIDE + sb]     = make_float2(v.x, v.y);
            hs[(2 * c + 1) * HS_STRIDE + sb] = make_float2(v.z, v.w);
        }
        // prefetch xp for this step while staging completes
        float2 xp0, xp1;
        if (khalf == 0) {
            xp0 = *(const float2*)&g_xp[dir][t][b0][n0];
            xp1 = *(const float2*)&g_xp[dir][t][b0 + 1][n0];
        }
        __syncthreads();

        ull a00 = 0ull, a01 = 0ull, a10 = 0ull, a11 = 0ull;
#pragma unroll 8
        for (int k2 = 0; k2 < 128; k2++) {
            ulonglong2 wv = *(const ulonglong2*)(wsp + k2 * WS_STRIDE);
            ulonglong2 hv = *(const ulonglong2*)(hsp + k2 * HS_STRIDE);
            fma2(a00, hv.x, wv.x); fma2(a01, hv.x, wv.y);
            fma2(a10, hv.y, wv.x); fma2(a11, hv.y, wv.y);
        }

        __syncthreads();   // hs reads done; safe to reuse as reduction scratch
        if (khalf == 1) {
            red[ctid * 2 + 0] = make_ulonglong2(a00, a01);
            red[ctid * 2 + 1] = make_ulonglong2(a10, a11);
        }
        __syncthreads();

        if (khalf == 0) {
            ulonglong2 p0 = red[ctid * 2 + 0];
            ulonglong2 p1 = red[ctid * 2 + 1];
            float2 s00 = unpack2(add2(a00, p0.x));
            float2 s01 = unpack2(add2(a01, p0.y));
            float2 s10 = unpack2(add2(a10, p1.x));
            float2 s11 = unpack2(add2(a11, p1.y));
            float v00 = tanhf(s00.x + s00.y + xp0.x);
            float v01 = tanhf(s01.x + s01.y + xp0.y);
            float v10 = tanhf(s10.x + s10.y + xp1.x);
            float v11 = tanhf(s11.x + s11.y + xp1.y);

            *(float2*)(hout + (size_t)b0 * HH + n0)       = make_float2(v00, v01);
            *(float2*)(hout + (size_t)(b0 + 1) * HH + n0) = make_float2(v10, v11);
            *(float2*)(out + ((size_t)b0 * TT + t) * (2 * HH) +
                       (size_t)dir * HH + n0) = make_float2(v00, v01);
            *(float2*)(out + ((size_t)(b0 + 1) * TT + t) * (2 * HH) +
                       (size_t)dir * HH + n0) = make_float2(v10, v11);
            if (s == TT - 1) {
                float* hT = out + (size_t)BB * TT * 2 * HH + (size_t)dir * BB * HH;
                *(float2*)(hT + (size_t)b0 * HH + n0)       = make_float2(v00, v01);
                *(float2*)(hT + (size_t)(b0 + 1) * HH + n0) = make_float2(v10, v11);
            }
        }
        if (s == TT - 1) break;

        // distributed-flag grid barrier (per direction)
        __syncthreads();                 // all hout writes issued
        if (tid == 0) st_rel(myflag, (unsigned)(s + 1));
        if (tid < 64) {
            const unsigned* f = &g_flag[dir][tid][0];
            while (ld_acq(f) < (unsigned)(s + 1)) {}
        }
        __syncthreads();
    }
}

extern "C" void kernel_launch(void* const* d_in, const int* in_sizes, int n_in,
                              void* d_out, int out_size) {
    const float* x     = (const float*)d_in[0];
    const float* h0f   = (const float*)d_in[1];
    const float* h0b   = (const float*)d_in[2];
    const float* Wxf_w = (const float*)d_in[3];
    const float* Wxf_b = (const float*)d_in[4];
    const float* Whf_w = (const float*)d_in[5];
    const float* Wxb_w = (const float*)d_in[6];
    const float* Wxb_b = (const float*)d_in[7];
    const float* Whb_w = (const float*)d_in[8];
    float* out = (float*)d_out;

    static int smem_set = 0;
    const int smem_bytes = 256 * WS_STRIDE * 8 + 256 * HS_STRIDE * 8;  // 106496
    if (!smem_set) {
        cudaFuncSetAttribute(rnn_persist,
                             cudaFuncAttributeMaxDynamicSharedMemorySize,
                             smem_bytes);
        smem_set = 1;
    }

    init_h_kernel<<<(BB * HH + 255) / 256, 256>>>(h0f, h0b);
    xproj_kernel<<<dim3(HH / 64, TT, 2), 256>>>(x, Wxf_w, Wxf_b, Wxb_w, Wxb_b);
    rnn_persist<<<128, 256, smem_bytes>>>(Whf_w, Whb_w, out);
}